// round 11
// baseline (speedup 1.0000x reference)
#include <cuda_runtime.h>
#include <cuda_fp16.h>

// Scratch (no allocation allowed): per-node gate values as fp16.
// N = 100000 <= 131072. Max rel rounding err ~2.4e-4 << 1e-3 tol.
#define MAX_NODES (1 << 17)
__device__ __align__(16) __half g_gate_h[MAX_NODES];

// ---------------------------------------------------------------------------
// Kernel 1: gate[n] = sigmoid(dot(x[n,:], p) + b). Warp-per-row GEMV
// (R8-proven inner loop), 512-thread blocks -> 16 rows/block, halving block
// count and p_sh fill overhead vs the 256-thread launch.
// ---------------------------------------------------------------------------
__global__ void __launch_bounds__(512) gate_kernel(
        const float* __restrict__ x,
        const float* __restrict__ p,
        const float* __restrict__ bptr,
        int N, int D) {
    __shared__ float p_sh[1024];
    int tid = threadIdx.x;
    for (int i = tid; i < D; i += blockDim.x) p_sh[i] = p[i];
    __syncthreads();

    int warp = tid >> 5;
    int lane = tid & 31;
    int row  = blockIdx.x * (blockDim.x >> 5) + warp;
    if (row >= N) return;

    const float4* xr = reinterpret_cast<const float4*>(x + (long long)row * D);
    float sum = 0.0f;
    int nvec = D >> 2;
    for (int i = lane; i < nvec; i += 32) {
        float4 xv = xr[i];
        float4 pv = reinterpret_cast<const float4*>(p_sh)[i];
        sum = fmaf(xv.x, pv.x, sum);
        sum = fmaf(xv.y, pv.y, sum);
        sum = fmaf(xv.z, pv.z, sum);
        sum = fmaf(xv.w, pv.w, sum);
    }
    #pragma unroll
    for (int o = 16; o > 0; o >>= 1)
        sum += __shfl_down_sync(0xffffffffu, sum, o);

    if (lane == 0) {
        float v = sum + bptr[0];
        g_gate_h[row] = __float2half_rn(1.0f / (1.0f + __expf(-v)));
    }
}

// ---------------------------------------------------------------------------
// Kernel 2 (smem variant): persistent CTAs stage the fp16 gate table into
// dynamic smem, then process 4 edges/thread/iter with software-pipelined
// prefetch of the NEXT grid-stride iteration (lane-contiguous addresses).
// Index width detected block-locally (int64 -> all high words zero).
// EXACT R8-proven form: 29.2us = 7.0 TB/s, at the LTS cap. Do not touch.
// ---------------------------------------------------------------------------
template <bool FULL>
__global__ void __launch_bounds__(1024) edge_smem_kernel(
        const void* __restrict__ eiv,
        const float* __restrict__ attr,
        float* __restrict__ out, int E, int N) {
    extern __shared__ __half gate_sh[];
    int tid = threadIdx.x;

    // --- block-local index-width detection ---
    int nz = 0;
    {
        const int* w = (const int*)eiv;
        int lim = E < 2048 ? E : 2048;
        for (int i = tid; i < lim; i += blockDim.x)
            if (w[2 * i + 1] != 0) nz = 1;
    }
    const int is64 = !__syncthreads_or(nz);

    // --- stage gate table: global fp16 -> smem (16B vector copies) ---
    {
        int nvec = (N * 2 + 15) >> 4;
        const uint4* src = reinterpret_cast<const uint4*>(g_gate_h);
        uint4* dst = reinterpret_cast<uint4*>(gate_sh);
        for (int i = tid; i < nvec; i += blockDim.x) dst[i] = src[i];
    }
    __syncthreads();

    int ngroups = E >> 2;                      // full 4-edge groups
    int stride  = gridDim.x * blockDim.x;
    const float4* attr4 = reinterpret_cast<const float4*>(attr);
    float4* o0 = reinterpret_cast<float4*>(out);
    float4* o1 = reinterpret_cast<float4*>(out + E);
    float4* o2 = reinterpret_cast<float4*>(out + 2 * (size_t)E);

    int g = blockIdx.x * blockDim.x + tid;

    if (is64) {
        const int4* r1p = reinterpret_cast<const int4*>((const long long*)eiv + E);
        const int4* r0p = reinterpret_cast<const int4*>(eiv);
        float4 av; int4 b0, b1, a0, a1;
        if (g < ngroups) {
            av = attr4[g];
            b0 = r1p[2 * g]; b1 = r1p[2 * g + 1];
            if (FULL) { a0 = r0p[2 * g]; a1 = r0p[2 * g + 1]; }
        }
        while (g < ngroups) {
            int gn = g + stride;
            float4 avn; int4 b0n, b1n, a0n, a1n;
            if (gn < ngroups) {   // prefetch next iteration (lane-contiguous)
                avn = attr4[gn];
                b0n = r1p[2 * gn]; b1n = r1p[2 * gn + 1];
                if (FULL) { a0n = r0p[2 * gn]; a1n = r0p[2 * gn + 1]; }
            }
            float4 adj;
            adj.x = av.x * __half2float(gate_sh[b0.x]);
            adj.y = av.y * __half2float(gate_sh[b0.z]);
            adj.z = av.z * __half2float(gate_sh[b1.x]);
            adj.w = av.w * __half2float(gate_sh[b1.z]);
            if (FULL) {
                o0[g] = make_float4(__int2float_rn(a0.x), __int2float_rn(a0.z),
                                    __int2float_rn(a1.x), __int2float_rn(a1.z));
                o1[g] = make_float4(__int2float_rn(b0.x), __int2float_rn(b0.z),
                                    __int2float_rn(b1.x), __int2float_rn(b1.z));
                o2[g] = adj;
            } else {
                o0[g] = adj;
            }
            g = gn; av = avn; b0 = b0n; b1 = b1n;
            if (FULL) { a0 = a0n; a1 = a1n; }
        }
    } else {
        const int4* bi = reinterpret_cast<const int4*>((const int*)eiv + E);
        const int4* ai = reinterpret_cast<const int4*>(eiv);
        float4 av; int4 b, a;
        if (g < ngroups) {
            av = attr4[g];
            b = bi[g];
            if (FULL) a = ai[g];
        }
        while (g < ngroups) {
            int gn = g + stride;
            float4 avn; int4 bn, an;
            if (gn < ngroups) {
                avn = attr4[gn];
                bn = bi[gn];
                if (FULL) an = ai[gn];
            }
            float4 adj;
            adj.x = av.x * __half2float(gate_sh[b.x]);
            adj.y = av.y * __half2float(gate_sh[b.y]);
            adj.z = av.z * __half2float(gate_sh[b.z]);
            adj.w = av.w * __half2float(gate_sh[b.w]);
            if (FULL) {
                o0[g] = make_float4(__int2float_rn(a.x), __int2float_rn(a.y),
                                    __int2float_rn(a.z), __int2float_rn(a.w));
                o1[g] = make_float4(__int2float_rn(b.x), __int2float_rn(b.y),
                                    __int2float_rn(b.z), __int2float_rn(b.w));
                o2[g] = adj;
            } else {
                o0[g] = adj;
            }
            g = gn; av = avn; b = bn;
            if (FULL) a = an;
        }
    }

    // --- tail: remaining E % 4 edges, first warp of block 0 ---
    if (blockIdx.x == 0 && tid < 32) {
        for (int k = (ngroups << 2) + tid; k < E; k += 32) {
            int c0, c1;
            if (is64) {
                const long long* ei = (const long long*)eiv;
                c0 = (int)ei[k];
                c1 = (int)ei[E + k];
            } else {
                const int* ei = (const int*)eiv;
                c0 = ei[k];
                c1 = ei[E + k];
            }
            float aval = attr[k] * __half2float(gate_sh[c1]);
            if (FULL) {
                out[k]                 = (float)c0;
                out[(size_t)E + k]     = (float)c1;
                out[2 * (size_t)E + k] = aval;
            } else {
                out[k] = aval;
            }
        }
    }
}

// ---------------------------------------------------------------------------
// Kernel 2 fallback (L2 gather) for N too large for smem.
// ---------------------------------------------------------------------------
template <bool FULL>
__global__ void __launch_bounds__(256) edge_l2_kernel(
        const void* __restrict__ eiv,
        const float* __restrict__ attr,
        float* __restrict__ out, int E) {
    int nz = 0;
    {
        const int* w = (const int*)eiv;
        int lim = E < 2048 ? E : 2048;
        for (int i = threadIdx.x; i < lim; i += blockDim.x)
            if (w[2 * i + 1] != 0) nz = 1;
    }
    const int is64 = !__syncthreads_or(nz);

    int g = blockIdx.x * blockDim.x + threadIdx.x;
    int e = g << 2;
    if (e >= E) return;
    if (e + 3 < E) {
        float4 av = reinterpret_cast<const float4*>(attr)[g];
        float4 adj, o0, o1;
        if (is64) {
            const int4* r1p = reinterpret_cast<const int4*>((const long long*)eiv + E);
            int4 b0 = r1p[2 * g];
            int4 b1 = r1p[2 * g + 1];
            adj.x = av.x * __half2float(g_gate_h[b0.x]);
            adj.y = av.y * __half2float(g_gate_h[b0.z]);
            adj.z = av.z * __half2float(g_gate_h[b1.x]);
            adj.w = av.w * __half2float(g_gate_h[b1.z]);
            if (FULL) {
                const int4* r0p = reinterpret_cast<const int4*>(eiv);
                int4 a0 = r0p[2 * g];
                int4 a1 = r0p[2 * g + 1];
                o0 = make_float4(__int2float_rn(a0.x), __int2float_rn(a0.z),
                                 __int2float_rn(a1.x), __int2float_rn(a1.z));
                o1 = make_float4(__int2float_rn(b0.x), __int2float_rn(b0.z),
                                 __int2float_rn(b1.x), __int2float_rn(b1.z));
            }
        } else {
            const int* ei = (const int*)eiv;
            int4 b = reinterpret_cast<const int4*>(ei + E)[g];
            adj.x = av.x * __half2float(g_gate_h[b.x]);
            adj.y = av.y * __half2float(g_gate_h[b.y]);
            adj.z = av.z * __half2float(g_gate_h[b.z]);
            adj.w = av.w * __half2float(g_gate_h[b.w]);
            if (FULL) {
                int4 a = reinterpret_cast<const int4*>(ei)[g];
                o0 = make_float4(__int2float_rn(a.x), __int2float_rn(a.y),
                                 __int2float_rn(a.z), __int2float_rn(a.w));
                o1 = make_float4(__int2float_rn(b.x), __int2float_rn(b.y),
                                 __int2float_rn(b.z), __int2float_rn(b.w));
            }
        }
        if (FULL) {
            reinterpret_cast<float4*>(out)[g] = o0;
            reinterpret_cast<float4*>(out + E)[g] = o1;
            reinterpret_cast<float4*>(out + 2 * (size_t)E)[g] = adj;
        } else {
            reinterpret_cast<float4*>(out)[g] = adj;
        }
    } else {
        for (int k = e; k < E; k++) {
            int c0, c1;
            if (is64) {
                const long long* ei = (const long long*)eiv;
                c0 = (int)ei[k];
                c1 = (int)ei[E + k];
            } else {
                const int* ei = (const int*)eiv;
                c0 = ei[k];
                c1 = ei[E + k];
            }
            float a = attr[k] * __half2float(g_gate_h[c1]);
            if (FULL) {
                out[k]                 = (float)c0;
                out[(size_t)E + k]     = (float)c1;
                out[2 * (size_t)E + k] = a;
            } else {
                out[k] = a;
            }
        }
    }
}

// ---------------------------------------------------------------------------
// Inputs (metadata order): x [N*D] f32, edge_index [2*E] (i32 or i64),
//                          edge_attr [E] f32, p [D] f32, b [1] f32
// ---------------------------------------------------------------------------
extern "C" void kernel_launch(void* const* d_in, const int* in_sizes, int n_in,
                              void* d_out, int out_size) {
    const float* x    = (const float*)d_in[0];
    const void*  ei   = d_in[1];
    const float* attr = (const float*)d_in[2];
    const float* p    = (const float*)d_in[3];
    const float* b    = (const float*)d_in[4];
    float* out = (float*)d_out;

    int ND = in_sizes[0];
    int E  = in_sizes[2];
    int D  = in_sizes[3];
    int N  = ND / D;

    // Kernel 1: per-node gates (fp16 table), 16 rows per 512-thread block.
    int gblocks = (N + 15) / 16;
    gate_kernel<<<gblocks, 512>>>(x, p, b, N, D);

    bool full = ((long long)out_size >= 3LL * E);
    int smem_bytes = ((N * 2 + 15) >> 4) << 4;   // fp16 table, 16B aligned

    if (N <= MAX_NODES && smem_bytes <= 225 * 1024) {
        if (full) {
            cudaFuncSetAttribute(edge_smem_kernel<true>,
                                 cudaFuncAttributeMaxDynamicSharedMemorySize, smem_bytes);
            edge_smem_kernel<true><<<152, 1024, smem_bytes>>>(ei, attr, out, E, N);
        } else {
            cudaFuncSetAttribute(edge_smem_kernel<false>,
                                 cudaFuncAttributeMaxDynamicSharedMemorySize, smem_bytes);
            edge_smem_kernel<false><<<152, 1024, smem_bytes>>>(ei, attr, out, E, N);
        }
    } else {
        int groups  = (E + 3) / 4;
        int eblocks = (groups + 255) / 256;
        if (full) edge_l2_kernel<true><<<eblocks, 256>>>(ei, attr, out, E);
        else      edge_l2_kernel<false><<<eblocks, 256>>>(ei, attr, out, E);
    }
}

// round 12
// speedup vs baseline: 1.1570x; 1.1570x over previous
#include <cuda_runtime.h>
#include <cuda_fp16.h>

// Scratch (no allocation allowed): per-node gate values as fp16.
// N = 100000 <= 131072. Max rel rounding err ~2.4e-4 << 1e-3 tol.
#define MAX_NODES (1 << 17)
__device__ __align__(16) __half g_gate_h[MAX_NODES];

// ---------------------------------------------------------------------------
// Kernel 1: gate[n] = sigmoid(dot(x[n,:], p) + b). Warp-per-row GEMV,
// p staged in shared, x read coalesced via float4. R8-proven form
// (~32us / 6.4 TB/s). 256-thread blocks, 8 rows/block.
// ---------------------------------------------------------------------------
__global__ void __launch_bounds__(256) gate_kernel(
        const float* __restrict__ x,
        const float* __restrict__ p,
        const float* __restrict__ bptr,
        int N, int D) {
    __shared__ float p_sh[1024];
    int tid = threadIdx.x;
    for (int i = tid; i < D; i += blockDim.x) p_sh[i] = p[i];
    __syncthreads();

    int warp = tid >> 5;
    int lane = tid & 31;
    int row  = blockIdx.x * (blockDim.x >> 5) + warp;
    if (row >= N) return;

    const float4* xr = reinterpret_cast<const float4*>(x + (long long)row * D);
    float sum = 0.0f;
    int nvec = D >> 2;
    for (int i = lane; i < nvec; i += 32) {
        float4 xv = xr[i];
        float4 pv = reinterpret_cast<const float4*>(p_sh)[i];
        sum = fmaf(xv.x, pv.x, sum);
        sum = fmaf(xv.y, pv.y, sum);
        sum = fmaf(xv.z, pv.z, sum);
        sum = fmaf(xv.w, pv.w, sum);
    }
    #pragma unroll
    for (int o = 16; o > 0; o >>= 1)
        sum += __shfl_down_sync(0xffffffffu, sum, o);

    if (lane == 0) {
        float v = sum + bptr[0];
        g_gate_h[row] = __float2half_rn(1.0f / (1.0f + __expf(-v)));
    }
}

// ---------------------------------------------------------------------------
// Kernel 2 (smem variant): persistent CTAs stage the fp16 gate table into
// dynamic smem, then process 4 edges/thread/iter with software-pipelined
// prefetch of the NEXT grid-stride iteration (lane-contiguous addresses).
// Index width detected block-locally (int64 -> all high words zero).
// R8-proven form: ~29us = 7.0 TB/s on clean runs, at the LTS cap.
// ---------------------------------------------------------------------------
template <bool FULL>
__global__ void __launch_bounds__(1024) edge_smem_kernel(
        const void* __restrict__ eiv,
        const float* __restrict__ attr,
        float* __restrict__ out, int E, int N) {
    extern __shared__ __half gate_sh[];
    int tid = threadIdx.x;

    // --- block-local index-width detection ---
    int nz = 0;
    {
        const int* w = (const int*)eiv;
        int lim = E < 2048 ? E : 2048;
        for (int i = tid; i < lim; i += blockDim.x)
            if (w[2 * i + 1] != 0) nz = 1;
    }
    const int is64 = !__syncthreads_or(nz);

    // --- stage gate table: global fp16 -> smem (16B vector copies) ---
    {
        int nvec = (N * 2 + 15) >> 4;
        const uint4* src = reinterpret_cast<const uint4*>(g_gate_h);
        uint4* dst = reinterpret_cast<uint4*>(gate_sh);
        for (int i = tid; i < nvec; i += blockDim.x) dst[i] = src[i];
    }
    __syncthreads();

    int ngroups = E >> 2;                      // full 4-edge groups
    int stride  = gridDim.x * blockDim.x;
    const float4* attr4 = reinterpret_cast<const float4*>(attr);
    float4* o0 = reinterpret_cast<float4*>(out);
    float4* o1 = reinterpret_cast<float4*>(out + E);
    float4* o2 = reinterpret_cast<float4*>(out + 2 * (size_t)E);

    int g = blockIdx.x * blockDim.x + tid;

    if (is64) {
        const int4* r1p = reinterpret_cast<const int4*>((const long long*)eiv + E);
        const int4* r0p = reinterpret_cast<const int4*>(eiv);
        float4 av; int4 b0, b1, a0, a1;
        if (g < ngroups) {
            av = attr4[g];
            b0 = r1p[2 * g]; b1 = r1p[2 * g + 1];
            if (FULL) { a0 = r0p[2 * g]; a1 = r0p[2 * g + 1]; }
        }
        while (g < ngroups) {
            int gn = g + stride;
            float4 avn; int4 b0n, b1n, a0n, a1n;
            if (gn < ngroups) {   // prefetch next iteration (lane-contiguous)
                avn = attr4[gn];
                b0n = r1p[2 * gn]; b1n = r1p[2 * gn + 1];
                if (FULL) { a0n = r0p[2 * gn]; a1n = r0p[2 * gn + 1]; }
            }
            float4 adj;
            adj.x = av.x * __half2float(gate_sh[b0.x]);
            adj.y = av.y * __half2float(gate_sh[b0.z]);
            adj.z = av.z * __half2float(gate_sh[b1.x]);
            adj.w = av.w * __half2float(gate_sh[b1.z]);
            if (FULL) {
                o0[g] = make_float4(__int2float_rn(a0.x), __int2float_rn(a0.z),
                                    __int2float_rn(a1.x), __int2float_rn(a1.z));
                o1[g] = make_float4(__int2float_rn(b0.x), __int2float_rn(b0.z),
                                    __int2float_rn(b1.x), __int2float_rn(b1.z));
                o2[g] = adj;
            } else {
                o0[g] = adj;
            }
            g = gn; av = avn; b0 = b0n; b1 = b1n;
            if (FULL) { a0 = a0n; a1 = a1n; }
        }
    } else {
        const int4* bi = reinterpret_cast<const int4*>((const int*)eiv + E);
        const int4* ai = reinterpret_cast<const int4*>(eiv);
        float4 av; int4 b, a;
        if (g < ngroups) {
            av = attr4[g];
            b = bi[g];
            if (FULL) a = ai[g];
        }
        while (g < ngroups) {
            int gn = g + stride;
            float4 avn; int4 bn, an;
            if (gn < ngroups) {
                avn = attr4[gn];
                bn = bi[gn];
                if (FULL) an = ai[gn];
            }
            float4 adj;
            adj.x = av.x * __half2float(gate_sh[b.x]);
            adj.y = av.y * __half2float(gate_sh[b.y]);
            adj.z = av.z * __half2float(gate_sh[b.z]);
            adj.w = av.w * __half2float(gate_sh[b.w]);
            if (FULL) {
                o0[g] = make_float4(__int2float_rn(a.x), __int2float_rn(a.y),
                                    __int2float_rn(a.z), __int2float_rn(a.w));
                o1[g] = make_float4(__int2float_rn(b.x), __int2float_rn(b.y),
                                    __int2float_rn(b.z), __int2float_rn(b.w));
                o2[g] = adj;
            } else {
                o0[g] = adj;
            }
            g = gn; av = avn; b = bn;
            if (FULL) a = an;
        }
    }

    // --- tail: remaining E % 4 edges, first warp of block 0 ---
    if (blockIdx.x == 0 && tid < 32) {
        for (int k = (ngroups << 2) + tid; k < E; k += 32) {
            int c0, c1;
            if (is64) {
                const long long* ei = (const long long*)eiv;
                c0 = (int)ei[k];
                c1 = (int)ei[E + k];
            } else {
                const int* ei = (const int*)eiv;
                c0 = ei[k];
                c1 = ei[E + k];
            }
            float aval = attr[k] * __half2float(gate_sh[c1]);
            if (FULL) {
                out[k]                 = (float)c0;
                out[(size_t)E + k]     = (float)c1;
                out[2 * (size_t)E + k] = aval;
            } else {
                out[k] = aval;
            }
        }
    }
}

// ---------------------------------------------------------------------------
// Kernel 2 fallback (L2 gather) for N too large for smem.
// ---------------------------------------------------------------------------
template <bool FULL>
__global__ void __launch_bounds__(256) edge_l2_kernel(
        const void* __restrict__ eiv,
        const float* __restrict__ attr,
        float* __restrict__ out, int E) {
    int nz = 0;
    {
        const int* w = (const int*)eiv;
        int lim = E < 2048 ? E : 2048;
        for (int i = threadIdx.x; i < lim; i += blockDim.x)
            if (w[2 * i + 1] != 0) nz = 1;
    }
    const int is64 = !__syncthreads_or(nz);

    int g = blockIdx.x * blockDim.x + threadIdx.x;
    int e = g << 2;
    if (e >= E) return;
    if (e + 3 < E) {
        float4 av = reinterpret_cast<const float4*>(attr)[g];
        float4 adj, o0, o1;
        if (is64) {
            const int4* r1p = reinterpret_cast<const int4*>((const long long*)eiv + E);
            int4 b0 = r1p[2 * g];
            int4 b1 = r1p[2 * g + 1];
            adj.x = av.x * __half2float(g_gate_h[b0.x]);
            adj.y = av.y * __half2float(g_gate_h[b0.z]);
            adj.z = av.z * __half2float(g_gate_h[b1.x]);
            adj.w = av.w * __half2float(g_gate_h[b1.z]);
            if (FULL) {
                const int4* r0p = reinterpret_cast<const int4*>(eiv);
                int4 a0 = r0p[2 * g];
                int4 a1 = r0p[2 * g + 1];
                o0 = make_float4(__int2float_rn(a0.x), __int2float_rn(a0.z),
                                 __int2float_rn(a1.x), __int2float_rn(a1.z));
                o1 = make_float4(__int2float_rn(b0.x), __int2float_rn(b0.z),
                                 __int2float_rn(b1.x), __int2float_rn(b1.z));
            }
        } else {
            const int* ei = (const int*)eiv;
            int4 b = reinterpret_cast<const int4*>(ei + E)[g];
            adj.x = av.x * __half2float(g_gate_h[b.x]);
            adj.y = av.y * __half2float(g_gate_h[b.y]);
            adj.z = av.z * __half2float(g_gate_h[b.z]);
            adj.w = av.w * __half2float(g_gate_h[b.w]);
            if (FULL) {
                int4 a = reinterpret_cast<const int4*>(ei)[g];
                o0 = make_float4(__int2float_rn(a.x), __int2float_rn(a.y),
                                 __int2float_rn(a.z), __int2float_rn(a.w));
                o1 = make_float4(__int2float_rn(b.x), __int2float_rn(b.y),
                                 __int2float_rn(b.z), __int2float_rn(b.w));
            }
        }
        if (FULL) {
            reinterpret_cast<float4*>(out)[g] = o0;
            reinterpret_cast<float4*>(out + E)[g] = o1;
            reinterpret_cast<float4*>(out + 2 * (size_t)E)[g] = adj;
        } else {
            reinterpret_cast<float4*>(out)[g] = adj;
        }
    } else {
        for (int k = e; k < E; k++) {
            int c0, c1;
            if (is64) {
                const long long* ei = (const long long*)eiv;
                c0 = (int)ei[k];
                c1 = (int)ei[E + k];
            } else {
                const int* ei = (const int*)eiv;
                c0 = ei[k];
                c1 = ei[E + k];
            }
            float a = attr[k] * __half2float(g_gate_h[c1]);
            if (FULL) {
                out[k]                 = (float)c0;
                out[(size_t)E + k]     = (float)c1;
                out[2 * (size_t)E + k] = a;
            } else {
                out[k] = a;
            }
        }
    }
}

// ---------------------------------------------------------------------------
// Inputs (metadata order): x [N*D] f32, edge_index [2*E] (i32 or i64),
//                          edge_attr [E] f32, p [D] f32, b [1] f32
// ---------------------------------------------------------------------------
extern "C" void kernel_launch(void* const* d_in, const int* in_sizes, int n_in,
                              void* d_out, int out_size) {
    const float* x    = (const float*)d_in[0];
    const void*  ei   = d_in[1];
    const float* attr = (const float*)d_in[2];
    const float* p    = (const float*)d_in[3];
    const float* b    = (const float*)d_in[4];
    float* out = (float*)d_out;

    int ND = in_sizes[0];
    int E  = in_sizes[2];
    int D  = in_sizes[3];
    int N  = ND / D;

    // Kernel 1: per-node gates (fp16 table), 8 rows per 256-thread block.
    int gblocks = (N + 7) / 8;
    gate_kernel<<<gblocks, 256>>>(x, p, b, N, D);

    bool full = ((long long)out_size >= 3LL * E);
    int smem_bytes = ((N * 2 + 15) >> 4) << 4;   // fp16 table, 16B aligned

    if (N <= MAX_NODES && smem_bytes <= 225 * 1024) {
        if (full) {
            cudaFuncSetAttribute(edge_smem_kernel<true>,
                                 cudaFuncAttributeMaxDynamicSharedMemorySize, smem_bytes);
            edge_smem_kernel<true><<<152, 1024, smem_bytes>>>(ei, attr, out, E, N);
        } else {
            cudaFuncSetAttribute(edge_smem_kernel<false>,
                                 cudaFuncAttributeMaxDynamicSharedMemorySize, smem_bytes);
            edge_smem_kernel<false><<<152, 1024, smem_bytes>>>(ei, attr, out, E, N);
        }
    } else {
        int groups  = (E + 3) / 4;
        int eblocks = (groups + 255) / 256;
        if (full) edge_l2_kernel<true><<<eblocks, 256>>>(ei, attr, out, E);
        else      edge_l2_kernel<false><<<eblocks, 256>>>(ei, attr, out, E);
    }
}